// round 15
// baseline (speedup 1.0000x reference)
#include <cuda_runtime.h>
#include <cuda_fp16.h>
#include <cstdint>

#define N_ROWS   2048
#define DIM_D    512
#define DIM_H    512
#define N_HEADS  16
#define MAXM     512

// ---------------- portable PTX helpers (sm_80-level only) --------------------
__device__ __forceinline__ uint32_t smem_to_u32(const void* p) {
    uint32_t a;
    asm("{ .reg .u64 t; cvta.to.shared.u64 t, %1; cvt.u32.u64 %0, t; }" : "=r"(a) : "l"(p));
    return a;
}
__device__ __forceinline__ void cp_async16(uint32_t dst, const void* src, int src_bytes) {
    asm volatile("cp.async.cg.shared.global [%0], [%1], 16, %2;"
                 :: "r"(dst), "l"(src), "r"(src_bytes) : "memory");
}
#define CP_COMMIT() asm volatile("cp.async.commit_group;" ::: "memory")
#define CP_WAIT(n)  asm volatile("cp.async.wait_group %0;" :: "n"(n) : "memory")
#define BAR_SYNC(id, cnt) asm volatile("bar.sync %0, %1;" :: "r"(id), "r"(cnt) : "memory")

__device__ __forceinline__ void ldsm_x4(uint32_t* r, uint32_t addr) {
    asm volatile("ldmatrix.sync.aligned.m8n8.x4.shared.b16 {%0,%1,%2,%3}, [%4];"
                 : "=r"(r[0]), "=r"(r[1]), "=r"(r[2]), "=r"(r[3]) : "r"(addr));
}
// fp16 inputs, fp32 accumulate
__device__ __forceinline__ void mma16816(float* d, const uint32_t* a, uint32_t b0, uint32_t b1) {
    asm volatile("mma.sync.aligned.m16n8k16.row.col.f32.f16.f16.f32 "
                 "{%0,%1,%2,%3}, {%4,%5,%6,%7}, {%8,%9}, {%0,%1,%2,%3};"
                 : "+f"(d[0]), "+f"(d[1]), "+f"(d[2]), "+f"(d[3])
                 : "r"(a[0]), "r"(a[1]), "r"(a[2]), "r"(a[3]), "r"(b0), "r"(b1));
}

// ---------------- device scratch (no allocations allowed) --------------------
__device__ int g_counts[N_HEADS];
__device__ int g_rows[N_HEADS * MAXM];
__device__ int g_work[64];          // (head << 16) | mtile  (BM=64 tiles, max 48)
__device__ int g_nwork;
__device__ __align__(256) __half g_Ih[N_ROWS * DIM_D];            // inputs fp16
__device__ __align__(256) __half g_Wt[N_HEADS * DIM_H * DIM_D];   // W^T fp16 [head][h][d]

// ============================================================================
// Fused prep kernel (identical to R12).
// ============================================================================
#define WT_BLOCKS   (N_HEADS * 16 * 16)
#define BKT_BLOCK   WT_BLOCKS
#define IN_BLOCKS   (N_ROWS * DIM_D / 4 / 256)
#define PREP_BLOCKS (WT_BLOCKS + 1 + IN_BLOCKS)

__global__ __launch_bounds__(256)
void prep_kernel(const float* __restrict__ inp,
                 const int* __restrict__ idx32,
                 const float* __restrict__ W) {
    const int b = blockIdx.x;
    const int tid = threadIdx.x;

    if (b < WT_BLOCKS) {
        __shared__ float t[32][33];
        const int head  = b >> 8;
        const int hTile = (b >> 4) & 15;
        const int dTile = b & 15;
        const int tx = tid & 31, ty = tid >> 5;   // 32 x 8
        const float* Wh = W + (size_t)head * DIM_D * DIM_H;
        const int d0 = dTile * 32, h0 = hTile * 32;
        #pragma unroll
        for (int i = 0; i < 4; i++)
            t[ty + i * 8][tx] = Wh[(size_t)(d0 + ty + i * 8) * DIM_H + h0 + tx];
        __syncthreads();
        __half* dst = g_Wt + (size_t)head * DIM_H * DIM_D;
        #pragma unroll
        for (int i = 0; i < 4; i++) {
            int hl = ty + i * 8;
            float v = t[tx][hl];          // = W[d0+tx][h0+hl]
            dst[(size_t)(h0 + hl) * DIM_D + d0 + tx] = __float2half(v);
        }
    } else if (b == BKT_BLOCK) {
        __shared__ int sc[N_HEADS];
        __shared__ int any_nonzero;
        if (tid == 0) any_nonzero = 0;
        if (tid < N_HEADS) sc[tid] = 0;
        __syncthreads();
        int local = 0;
        for (int i = 1 + 2 * tid; i < N_ROWS; i += 2 * 256) local |= idx32[i];
        if (local) atomicOr(&any_nonzero, 1);
        __syncthreads();
        const int is64 = (any_nonzero == 0);
        for (int i = tid; i < N_ROWS; i += 256) {
            int h = (is64 ? idx32[2 * i] : idx32[i]) & (N_HEADS - 1);
            int pos = atomicAdd(&sc[h], 1);
            if (pos < MAXM) g_rows[h * MAXM + pos] = i;
        }
        __syncthreads();
        if (tid < N_HEADS) g_counts[tid] = min(sc[tid], MAXM);
        __syncthreads();
        if (tid == 0) {
            int n = 0;
            for (int h = 0; h < N_HEADS; h++) {
                int c = min(sc[h], MAXM);
                for (int mb = 0; mb * 64 < c; mb++) g_work[n++] = (h << 16) | mb;
            }
            g_nwork = n;   // Σceil(c/64) <= 2048/64 + 16 = 48
        }
    } else {
        const int cb = b - BKT_BLOCK - 1;
        const int e = (cb * 256 + tid) * 4;
        float4 v = *reinterpret_cast<const float4*>(inp + e);
        __half2 h01 = __halves2half2(__float2half(v.x), __float2half(v.y));
        __half2 h23 = __halves2half2(__float2half(v.z), __float2half(v.w));
        *reinterpret_cast<__half2*>(g_Ih + e)     = h01;
        *reinterpret_cast<__half2*>(g_Ih + e + 2) = h23;
    }
}

// ============================================================================
// Split-K-in-CTA fp16 HMMA GEMM. grid = (8 ntiles, 48 slots), 256 threads.
// Per CTA: D[64, 64]; two 4-warp groups, group g covers K in [g*256, g*256+256)
// over 4 chunks of 64, each group with its OWN 3-stage cp.async pipeline and
// group-local named barriers. Deterministic combine (g0 + g1) then epilogue.
// Warp tile 32x32: per k16-step 4 ldsm -> 8 independent MMAs.
// ============================================================================
#define BM 64
#define BN 64
#define BK 64
#define ROWB 144                   // 64 fp16 = 128B + 16B pad; mult of 16;
                                   // 144*r mod 128, r=0..7 -> 8 distinct banks
#define A_T (BM * ROWB)            // 9216 B
#define B_T (BN * ROWB)            // 9216 B
#define STAGE (A_T + B_T)          // 18432
#define NSTAGE 3
#define KSPLIT 2
#define KG (DIM_D / KSPLIT)        // 256 per group
#define NCHUNK_G (KG / BK)         // 4 chunks per group
#define OFF_ROWS 0                 // 64 ints
#define OFF_BIAS 256               // 64 floats
#define OFF_DATA 1024
#define GEMM_SMEM (OFF_DATA + KSPLIT * NSTAGE * STAGE)   // 111616 B

extern __shared__ char dyn_smem[];

__global__ __launch_bounds__(256, 2)
void gemm_kernel(const float* __restrict__ bias, float* __restrict__ out) {
    const int wy = blockIdx.y;
    if (wy >= g_nwork) return;
    const int item  = g_work[wy];
    const int head  = item >> 16;
    const int mbase = (item & 0xffff) * BM;
    const int nrows = g_counts[head];
    const int hbase = blockIdx.x * BN;

    const int tid  = threadIdx.x;
    const int lane = tid & 31;
    const int wid  = tid >> 5;
    const int g    = wid >> 2;       // k-split group 0/1
    const int lt   = tid & 127;      // thread id within group
    const int lw   = wid & 3;        // warp within group
    const int wm   = lw & 1;         // 2 warp-rows of 32
    const int wn   = lw >> 1;        // 2 warp-cols of 32

    const uint32_t smem_u32 = smem_to_u32(dyn_smem);
    int*   s_rows = reinterpret_cast<int*>(dyn_smem + OFF_ROWS);
    float* s_bias = reinterpret_cast<float*>(dyn_smem + OFF_BIAS);
    const uint32_t gdata = smem_u32 + OFF_DATA + (uint32_t)g * (NSTAGE * STAGE);
    const int kbase = g * KG;

    if (tid < BM) {
        int m = mbase + tid;
        s_rows[tid] = (m < nrows) ? g_rows[head * MAXM + m] : -1;
    }
    if (tid >= 64 && tid < 64 + BN)
        s_bias[tid - 64] = bias[head * DIM_H + hbase + (tid - 64)];
    __syncthreads();

    // ldmatrix per-lane base offsets
    const int lr8 = (lane & 7) + ((lane >> 3) & 1) * 8;
    const int kq  = (lane >> 4) * 16;
    const uint32_t a_off = (uint32_t)((wm * 32 + lr8) * ROWB + kq);
    const uint32_t b_off = (uint32_t)(A_T + (wn * 32 + lr8) * ROWB + kq);

    const __half* __restrict__ BtP = g_Wt + ((size_t)head * DIM_H + hbase) * DIM_D;

    float d[2][4][4];                 // [m-tile][n8-group][frag]
    #pragma unroll
    for (int i = 0; i < 2; i++)
        #pragma unroll
        for (int j = 0; j < 4; j++)
            #pragma unroll
            for (int k = 0; k < 4; k++) d[i][j][k] = 0.0f;

    // ---- group-local chunk loader: A (512 xfers) + B (512 xfers), 128 thr ----
    auto issue = [&](int ch) {
        const int koff = kbase + ch * BK;
        const uint32_t sb = gdata + (uint32_t)(ch % NSTAGE) * STAGE;
        #pragma unroll
        for (int j = 0; j < 4; j++) {                // A: 64 rows x 8 x 16B
            int u = lt + j * 128;
            int r = u >> 3, c = u & 7;
            int grow = s_rows[r];
            const __half* src = g_Ih + (size_t)max(grow, 0) * DIM_D + koff + c * 8;
            cp_async16(sb + r * ROWB + c * 16, src, grow >= 0 ? 16 : 0);
        }
        #pragma unroll
        for (int j = 0; j < 4; j++) {                // B: 64 rows x 8 x 16B
            int u = lt + j * 128;
            int n = u >> 3, c = u & 7;
            const __half* src = BtP + (size_t)n * DIM_D + koff + c * 8;
            cp_async16(sb + A_T + n * ROWB + c * 16, src, 16);
        }
        CP_COMMIT();
    };

    issue(0);
    issue(1);
    #pragma unroll 1
    for (int it = 0; it < NCHUNK_G; it++) {
        if (it < NCHUNK_G - 1) { CP_WAIT(1); }
        else                   { CP_WAIT(0); }
        BAR_SYNC(1 + g, 128);   // group-local: stage-it visible; old buffer free
        if (it + 2 < NCHUNK_G) issue(it + 2);

        const uint32_t sb = gdata + (uint32_t)(it % NSTAGE) * STAGE;
        #pragma unroll
        for (int ks = 0; ks < BK / 16; ks++) {
            const uint32_t kb = (uint32_t)(ks * 32);
            // 4 ldsm -> 8 independent MMAs
            uint32_t a0[4], a1[4], b0[4], b1[4];
            uint32_t ao = sb + a_off + kb;
            uint32_t bo = sb + b_off + kb;
            ldsm_x4(a0, ao);                 // m rows [wm*32,   +16)
            ldsm_x4(a1, ao + 16 * ROWB);     // m rows [wm*32+16, +16)
            ldsm_x4(b0, bo);                 // n cols [wn*32,   +16)
            ldsm_x4(b1, bo + 16 * ROWB);     // n cols [wn*32+16, +16)
            mma16816(d[0][0], a0, b0[0], b0[2]);
            mma16816(d[0][1], a0, b0[1], b0[3]);
            mma16816(d[0][2], a0, b1[0], b1[2]);
            mma16816(d[0][3], a0, b1[1], b1[3]);
            mma16816(d[1][0], a1, b0[0], b0[2]);
            mma16816(d[1][1], a1, b0[1], b0[3]);
            mma16816(d[1][2], a1, b1[0], b1[2]);
            mma16816(d[1][3], a1, b1[1], b1[3]);
        }
    }

    // ---- combine group partial sums (deterministic order: g0 + g1) ----
    __syncthreads();                  // both pipelines fully drained
    float* s_acc = reinterpret_cast<float*>(dyn_smem + OFF_DATA);
    if (g == 1) {
        #pragma unroll
        for (int m2 = 0; m2 < 2; m2++)
            #pragma unroll
            for (int n2 = 0; n2 < 4; n2++)
                #pragma unroll
                for (int k = 0; k < 4; k++)
                    s_acc[(lt * 32) + (m2 * 4 + n2) * 4 + k] = d[m2][n2][k];
    }
    __syncthreads();

    // ---- epilogue by group 0: add partner sums + bias, scatter ----
    if (g == 0) {
        #pragma unroll
        for (int m2 = 0; m2 < 2; m2++)
            #pragma unroll
            for (int n2 = 0; n2 < 4; n2++)
                #pragma unroll
                for (int k = 0; k < 4; k++)
                    d[m2][n2][k] += s_acc[(lt * 32) + (m2 * 4 + n2) * 4 + k];

        #pragma unroll
        for (int m2 = 0; m2 < 2; m2++) {
            const int r0 = wm * 32 + m2 * 16 + (lane >> 2);
            const int row0 = s_rows[r0];
            const int row1 = s_rows[r0 + 8];
            #pragma unroll
            for (int n2 = 0; n2 < 4; n2++) {
                const int col = wn * 32 + n2 * 8 + (lane & 3) * 2;
                const float bx = s_bias[col], by = s_bias[col + 1];
                if (row0 >= 0) {
                    float2 o = make_float2(d[m2][n2][0] + bx, d[m2][n2][1] + by);
                    *reinterpret_cast<float2*>(out + (size_t)row0 * DIM_H + hbase + col) = o;
                }
                if (row1 >= 0) {
                    float2 o = make_float2(d[m2][n2][2] + bx, d[m2][n2][3] + by);
                    *reinterpret_cast<float2*>(out + (size_t)row1 * DIM_H + hbase + col) = o;
                }
            }
        }
    }
}

extern "C" void kernel_launch(void* const* d_in, const int* in_sizes, int n_in,
                              void* d_out, int out_size) {
    const float* inp   = (const float*)d_in[0];
    const int*   idx32 = (const int*)d_in[1];   // int64 or int32 — detected on device
    const float* W     = (const float*)d_in[2];
    const float* bias  = (const float*)d_in[3];
    float*       out   = (float*)d_out;

    cudaFuncSetAttribute(gemm_kernel, cudaFuncAttributeMaxDynamicSharedMemorySize, GEMM_SMEM);

    prep_kernel<<<PREP_BLOCKS, 256>>>(inp, idx32, W);
    dim3 grid(DIM_H / BN, 48);   // max worklist = 2048/64 + 16 = 48
    gemm_kernel<<<grid, 256, GEMM_SMEM>>>(bias, out);
}

// round 16
// speedup vs baseline: 1.0843x; 1.0843x over previous
#include <cuda_runtime.h>
#include <cuda_fp16.h>
#include <cstdint>

#define N_ROWS   2048
#define DIM_D    512
#define DIM_H    512
#define N_HEADS  16
#define MAXM     512

// ---------------- portable PTX helpers (sm_80-level only) --------------------
__device__ __forceinline__ uint32_t smem_to_u32(const void* p) {
    uint32_t a;
    asm("{ .reg .u64 t; cvta.to.shared.u64 t, %1; cvt.u32.u64 %0, t; }" : "=r"(a) : "l"(p));
    return a;
}
__device__ __forceinline__ void cp_async16(uint32_t dst, const void* src, int src_bytes) {
    asm volatile("cp.async.cg.shared.global [%0], [%1], 16, %2;"
                 :: "r"(dst), "l"(src), "r"(src_bytes) : "memory");
}
#define CP_COMMIT() asm volatile("cp.async.commit_group;" ::: "memory")
#define CP_WAIT(n)  asm volatile("cp.async.wait_group %0;" :: "n"(n) : "memory")

__device__ __forceinline__ void ldsm_x4(uint32_t* r, uint32_t addr) {
    asm volatile("ldmatrix.sync.aligned.m8n8.x4.shared.b16 {%0,%1,%2,%3}, [%4];"
                 : "=r"(r[0]), "=r"(r[1]), "=r"(r[2]), "=r"(r[3]) : "r"(addr));
}
// fp16 inputs, fp32 accumulate
__device__ __forceinline__ void mma16816(float* d, const uint32_t* a, uint32_t b0, uint32_t b1) {
    asm volatile("mma.sync.aligned.m16n8k16.row.col.f32.f16.f16.f32 "
                 "{%0,%1,%2,%3}, {%4,%5,%6,%7}, {%8,%9}, {%0,%1,%2,%3};"
                 : "+f"(d[0]), "+f"(d[1]), "+f"(d[2]), "+f"(d[3])
                 : "r"(a[0]), "r"(a[1]), "r"(a[2]), "r"(a[3]), "r"(b0), "r"(b1));
}

// ---------------- device scratch (no allocations allowed) --------------------
__device__ int g_counts[N_HEADS];
__device__ int g_rows[N_HEADS * MAXM];
__device__ int g_work[64];          // (head << 16) | mtile  (BM=64 tiles, max 48)
__device__ int g_nwork;
__device__ __align__(256) __half g_Ih[N_ROWS * DIM_D];            // inputs fp16
__device__ __align__(256) __half g_Wt[N_HEADS * DIM_H * DIM_D];   // W^T fp16 [head][h][d]

// ============================================================================
// Fused prep kernel (identical to R12).
// ============================================================================
#define WT_BLOCKS   (N_HEADS * 16 * 16)
#define BKT_BLOCK   WT_BLOCKS
#define IN_BLOCKS   (N_ROWS * DIM_D / 4 / 256)
#define PREP_BLOCKS (WT_BLOCKS + 1 + IN_BLOCKS)

__global__ __launch_bounds__(256)
void prep_kernel(const float* __restrict__ inp,
                 const int* __restrict__ idx32,
                 const float* __restrict__ W) {
    const int b = blockIdx.x;
    const int tid = threadIdx.x;

    if (b < WT_BLOCKS) {
        __shared__ float t[32][33];
        const int head  = b >> 8;
        const int hTile = (b >> 4) & 15;
        const int dTile = b & 15;
        const int tx = tid & 31, ty = tid >> 5;   // 32 x 8
        const float* Wh = W + (size_t)head * DIM_D * DIM_H;
        const int d0 = dTile * 32, h0 = hTile * 32;
        #pragma unroll
        for (int i = 0; i < 4; i++)
            t[ty + i * 8][tx] = Wh[(size_t)(d0 + ty + i * 8) * DIM_H + h0 + tx];
        __syncthreads();
        __half* dst = g_Wt + (size_t)head * DIM_H * DIM_D;
        #pragma unroll
        for (int i = 0; i < 4; i++) {
            int hl = ty + i * 8;
            float v = t[tx][hl];          // = W[d0+tx][h0+hl]
            dst[(size_t)(h0 + hl) * DIM_D + d0 + tx] = __float2half(v);
        }
    } else if (b == BKT_BLOCK) {
        __shared__ int sc[N_HEADS];
        __shared__ int any_nonzero;
        if (tid == 0) any_nonzero = 0;
        if (tid < N_HEADS) sc[tid] = 0;
        __syncthreads();
        int local = 0;
        for (int i = 1 + 2 * tid; i < N_ROWS; i += 2 * 256) local |= idx32[i];
        if (local) atomicOr(&any_nonzero, 1);
        __syncthreads();
        const int is64 = (any_nonzero == 0);
        for (int i = tid; i < N_ROWS; i += 256) {
            int h = (is64 ? idx32[2 * i] : idx32[i]) & (N_HEADS - 1);
            int pos = atomicAdd(&sc[h], 1);
            if (pos < MAXM) g_rows[h * MAXM + pos] = i;
        }
        __syncthreads();
        if (tid < N_HEADS) g_counts[tid] = min(sc[tid], MAXM);
        __syncthreads();
        if (tid == 0) {
            int n = 0;
            for (int h = 0; h < N_HEADS; h++) {
                int c = min(sc[h], MAXM);
                for (int mb = 0; mb * 64 < c; mb++) g_work[n++] = (h << 16) | mb;
            }
            g_nwork = n;   // Σceil(c/64) <= 2048/64 + 16 = 48
        }
    } else {
        const int cb = b - BKT_BLOCK - 1;
        const int e = (cb * 256 + tid) * 4;
        float4 v = *reinterpret_cast<const float4*>(inp + e);
        __half2 h01 = __halves2half2(__float2half(v.x), __float2half(v.y));
        __half2 h23 = __halves2half2(__float2half(v.z), __float2half(v.w));
        *reinterpret_cast<__half2*>(g_Ih + e)     = h01;
        *reinterpret_cast<__half2*>(g_Ih + e + 2) = h23;
    }
}

// ============================================================================
// Single-pass fp16 HMMA GEMM (identical to R12) + full smem carveout so
// 4 CTAs/SM become resident (4 x 56.3KB = 225KB <= 228KB) -> single wave.
// grid = (H/64 = 8 ntiles, 48 work slots), 128 thr.
// Per CTA: D[64 rows, 64 cols], K=512, chunks of K=64 (8 chunks),
// 3-stage cp.async, one __syncthreads per chunk.
// 4 warps = 2m x 2n, warp tile 32x32: per k16-step 4 ldsm -> 8 independent MMAs.
// ============================================================================
#define BM 64
#define BN 64
#define BK 64
#define ROWB 144                   // 64 fp16 = 128B + 16B pad; mult of 16;
                                   // 144*r mod 128, r=0..7 -> 8 distinct banks
#define A_T (BM * ROWB)            // 9216 B
#define B_T (BN * ROWB)            // 9216 B
#define STAGE (A_T + B_T)          // 18432
#define NSTAGE 3
#define NCHUNK (DIM_D / BK)        // 8
#define OFF_ROWS 0                 // 64 ints
#define OFF_BIAS 256               // 64 floats
#define OFF_DATA 1024
#define GEMM_SMEM (OFF_DATA + NSTAGE * STAGE)   // 56320 B

extern __shared__ char dyn_smem[];

__global__ __launch_bounds__(128, 4)
void gemm_kernel(const float* __restrict__ bias, float* __restrict__ out) {
    const int wy = blockIdx.y;
    if (wy >= g_nwork) return;
    const int item  = g_work[wy];
    const int head  = item >> 16;
    const int mbase = (item & 0xffff) * BM;
    const int nrows = g_counts[head];
    const int hbase = blockIdx.x * BN;

    const int tid  = threadIdx.x;
    const int lane = tid & 31;
    const int wid  = tid >> 5;
    const int wm   = wid & 1;        // 2 warp-rows of 32
    const int wn   = wid >> 1;       // 2 warp-cols of 32

    const uint32_t smem_u32 = smem_to_u32(dyn_smem);
    int*   s_rows = reinterpret_cast<int*>(dyn_smem + OFF_ROWS);
    float* s_bias = reinterpret_cast<float*>(dyn_smem + OFF_BIAS);
    const uint32_t data_u32 = smem_u32 + OFF_DATA;

    if (tid < BM) {
        int m = mbase + tid;
        s_rows[tid] = (m < nrows) ? g_rows[head * MAXM + m] : -1;
    }
    if (tid >= 64 && tid < 64 + BN)
        s_bias[tid - 64] = bias[head * DIM_H + hbase + (tid - 64)];
    __syncthreads();

    // ldmatrix per-lane base offsets
    const int lr8 = (lane & 7) + ((lane >> 3) & 1) * 8;
    const int kq  = (lane >> 4) * 16;
    const uint32_t a_off = (uint32_t)((wm * 32 + lr8) * ROWB + kq);
    const uint32_t b_off = (uint32_t)(A_T + (wn * 32 + lr8) * ROWB + kq);

    const __half* __restrict__ BtP = g_Wt + ((size_t)head * DIM_H + hbase) * DIM_D;

    float d[2][4][4];                 // [m-tile][n8-group][frag]
    #pragma unroll
    for (int i = 0; i < 2; i++)
        #pragma unroll
        for (int j = 0; j < 4; j++)
            #pragma unroll
            for (int k = 0; k < 4; k++) d[i][j][k] = 0.0f;

    // ---- chunk loader: A (512 xfers) + B (512 xfers) ----
    auto issue = [&](int ch) {
        const int koff = ch * BK;
        const uint32_t sb = data_u32 + (uint32_t)(ch % NSTAGE) * STAGE;
        #pragma unroll
        for (int j = 0; j < 4; j++) {                // A: 64 rows x 8 x 16B
            int u = tid + j * 128;
            int r = u >> 3, c = u & 7;
            int grow = s_rows[r];
            const __half* src = g_Ih + (size_t)max(grow, 0) * DIM_D + koff + c * 8;
            cp_async16(sb + r * ROWB + c * 16, src, grow >= 0 ? 16 : 0);
        }
        #pragma unroll
        for (int j = 0; j < 4; j++) {                // B: 64 rows x 8 x 16B
            int u = tid + j * 128;
            int n = u >> 3, c = u & 7;
            const __half* src = BtP + (size_t)n * DIM_D + koff + c * 8;
            cp_async16(sb + A_T + n * ROWB + c * 16, src, 16);
        }
        CP_COMMIT();
    };

    issue(0);
    issue(1);
    #pragma unroll 1
    for (int it = 0; it < NCHUNK; it++) {
        if (it < NCHUNK - 1) { CP_WAIT(1); }
        else                 { CP_WAIT(0); }
        __syncthreads();   // stage-it data visible; buffer (it-1)%3 free
        if (it + 2 < NCHUNK) issue(it + 2);

        const uint32_t sb = data_u32 + (uint32_t)(it % NSTAGE) * STAGE;
        #pragma unroll
        for (int ks = 0; ks < BK / 16; ks++) {
            const uint32_t kb = (uint32_t)(ks * 32);
            // 4 ldsm -> 8 independent MMAs
            uint32_t a0[4], a1[4], b0[4], b1[4];
            uint32_t ao = sb + a_off + kb;
            uint32_t bo = sb + b_off + kb;
            ldsm_x4(a0, ao);                 // m rows [wm*32,   +16)
            ldsm_x4(a1, ao + 16 * ROWB);     // m rows [wm*32+16, +16)
            ldsm_x4(b0, bo);                 // n cols [wn*32,   +16)
            ldsm_x4(b1, bo + 16 * ROWB);     // n cols [wn*32+16, +16)
            mma16816(d[0][0], a0, b0[0], b0[2]);
            mma16816(d[0][1], a0, b0[1], b0[3]);
            mma16816(d[0][2], a0, b1[0], b1[2]);
            mma16816(d[0][3], a0, b1[1], b1[3]);
            mma16816(d[1][0], a1, b0[0], b0[2]);
            mma16816(d[1][1], a1, b0[1], b0[3]);
            mma16816(d[1][2], a1, b1[0], b1[2]);
            mma16816(d[1][3], a1, b1[1], b1[3]);
        }
    }

    // ---- epilogue: bias + scatter ----
    #pragma unroll
    for (int m2 = 0; m2 < 2; m2++) {
        const int r0 = wm * 32 + m2 * 16 + (lane >> 2);
        const int row0 = s_rows[r0];
        const int row1 = s_rows[r0 + 8];
        #pragma unroll
        for (int n2 = 0; n2 < 4; n2++) {
            const int col = wn * 32 + n2 * 8 + (lane & 3) * 2;
            const float bx = s_bias[col], by = s_bias[col + 1];
            if (row0 >= 0) {
                float2 o = make_float2(d[m2][n2][0] + bx, d[m2][n2][1] + by);
                *reinterpret_cast<float2*>(out + (size_t)row0 * DIM_H + hbase + col) = o;
            }
            if (row1 >= 0) {
                float2 o = make_float2(d[m2][n2][2] + bx, d[m2][n2][3] + by);
                *reinterpret_cast<float2*>(out + (size_t)row1 * DIM_H + hbase + col) = o;
            }
        }
    }
}

extern "C" void kernel_launch(void* const* d_in, const int* in_sizes, int n_in,
                              void* d_out, int out_size) {
    const float* inp   = (const float*)d_in[0];
    const int*   idx32 = (const int*)d_in[1];   // int64 or int32 — detected on device
    const float* W     = (const float*)d_in[2];
    const float* bias  = (const float*)d_in[3];
    float*       out   = (float*)d_out;

    cudaFuncSetAttribute(gemm_kernel, cudaFuncAttributeMaxDynamicSharedMemorySize, GEMM_SMEM);
    // Full 228KB carveout so 4 CTAs (4 x 56.3KB = 225KB) fit per SM -> 1 wave.
    cudaFuncSetAttribute(gemm_kernel, cudaFuncAttributePreferredSharedMemoryCarveout, 100);

    prep_kernel<<<PREP_BLOCKS, 256>>>(inp, idx32, W);
    dim3 grid(DIM_H / BN, 48);   // max worklist = 2048/64 + 16 = 48
    gemm_kernel<<<grid, 128, GEMM_SMEM>>>(bias, out);
}